// round 8
// baseline (speedup 1.0000x reference)
#include <cuda_runtime.h>
#include <cstdint>

#define DIN 512
#define DH  256
#define GNUM 128
#define NMAX 20000
#define EMAX 320000
#define CAP  96          // padded-CSR slots per node (Poisson(16) -> max deg ~45)

// ---- scratch (static __device__ globals; no allocation allowed) ----
__device__ float g_y[NMAX * DH];       // messages y = (A@W)*dinv[row]
__device__ float g_h[NMAX * DH];       // layer-1 output (GEMM-2 input)
__device__ int   g_icnt[NMAX];         // in-degree (excl. self) = fill cursor
__device__ int   g_eslot[NMAX * CAP];  // padded CSR: src per incoming edge
__device__ float g_pool[GNUM * DH];
__device__ float g_cnt[GNUM];

// ================= helpers =================
__device__ __forceinline__ float tf32r(float x) {
    uint32_t u;
    asm("cvt.rna.tf32.f32 %0, %1;" : "=r"(u) : "f"(x));
    return __uint_as_float(u);
}

__device__ __forceinline__ void mma_tf32(float* c, const uint32_t* a, const uint32_t* b) {
    asm volatile("mma.sync.aligned.m16n8k8.row.col.f32.tf32.tf32.f32 "
        "{%0,%1,%2,%3}, {%4,%5,%6,%7}, {%8,%9}, {%0,%1,%2,%3};"
        : "+f"(c[0]), "+f"(c[1]), "+f"(c[2]), "+f"(c[3])
        : "r"(a[0]), "r"(a[1]), "r"(a[2]), "r"(a[3]), "r"(b[0]), "r"(b[1]));
}

__device__ __forceinline__ void addf4(float* a, float4 v) {
    a[0] += v.x; a[1] += v.y; a[2] += v.z; a[3] += v.w;
}

// ================= prep: zero + padded-CSR fill =================
__global__ void k_zero(int N) {
    int t = blockIdx.x * blockDim.x + threadIdx.x;
    if (t < GNUM * DH) g_pool[t] = 0.f;
    if (t < GNUM) g_cnt[t] = 0.f;
    if (t < N) g_icnt[t] = 0;
}

__global__ void k_fill(const int* __restrict__ src, const int* __restrict__ dst, int E) {
    int e = blockIdx.x * blockDim.x + threadIdx.x;
    if (e >= E) return;
    int d = dst[e];
    int pos = atomicAdd(&g_icnt[d], 1);
    if (pos < CAP) g_eslot[d * CAP + pos] = src[e];
}

// ================= TF32 mma.sync GEMM: g_y = (A @ W) * dinv[row] =================
// CTA tile 160x128, BK=32, 10 warps, warptile 32x64 (2x8 m16n8k8 tiles).
#define AST 36
#define BST 136
#define AS_F (160 * AST)
#define BS_F (32 * BST)
#define SMEM_GEMM_BYTES ((2 * AS_F + 2 * BS_F) * 4)

template<int K, bool FROM_H>
__global__ void __launch_bounds__(320, 2)
k_gemm_mma(const float* __restrict__ Ax, const float* __restrict__ W, int M)
{
    extern __shared__ float sm[];
    const float* __restrict__ A = FROM_H ? (const float*)g_h : Ax;

    const int tid = threadIdx.x;
    const int wid = tid >> 5;
    const int lid = tid & 31;
    const int gid = lid >> 2;
    const int tig = lid & 3;
    const int warpM = wid % 5;
    const int warpN = wid / 5;
    const int rowBase = blockIdx.x * 160;
    const int colBase = blockIdx.y * 128;
    constexpr int NC = K / 32;

    float C[2][8][4];
    #pragma unroll
    for (int mt = 0; mt < 2; mt++)
        #pragma unroll
        for (int nt = 0; nt < 8; nt++)
            #pragma unroll
            for (int i = 0; i < 4; i++) C[mt][nt][i] = 0.f;

    auto stage = [&](int buf, int c) {
        float* As = sm + buf * AS_F;
        float* Bs = sm + 2 * AS_F + buf * BS_F;
        #pragma unroll
        for (int i = 0; i < 4; i++) {
            int idx = tid + i * 320;
            int m = idx >> 3, k4 = (idx & 7) << 2;
            int gr = rowBase + m;
            float4 v = make_float4(0.f, 0.f, 0.f, 0.f);
            if (gr < M) v = *(const float4*)(A + (size_t)gr * K + c * 32 + k4);
            v.x = tf32r(v.x); v.y = tf32r(v.y); v.z = tf32r(v.z); v.w = tf32r(v.w);
            *(float4*)&As[m * AST + k4] = v;
        }
        #pragma unroll
        for (int i = 0; i < 4; i++) {
            int idx = tid + i * 320;
            if (idx < 1024) {
                int k = idx >> 5, n4 = (idx & 31) << 2;
                float4 v = *(const float4*)(W + (size_t)(c * 32 + k) * DH + colBase + n4);
                v.x = tf32r(v.x); v.y = tf32r(v.y); v.z = tf32r(v.z); v.w = tf32r(v.w);
                *(float4*)&Bs[k * BST + n4] = v;
            }
        }
    };

    stage(0, 0);

    for (int c = 0; c < NC; c++) {
        __syncthreads();
        if (c + 1 < NC) stage((c + 1) & 1, c + 1);

        const int buf = c & 1;
        const float* As = sm + buf * AS_F;
        const float* Bs = sm + 2 * AS_F + buf * BS_F;

        #pragma unroll
        for (int ks = 0; ks < 4; ks++) {
            const int kk = ks * 8 + tig;
            uint32_t a[2][4];
            #pragma unroll
            for (int mt = 0; mt < 2; mt++) {
                int mr = warpM * 32 + mt * 16 + gid;
                a[mt][0] = __float_as_uint(As[mr * AST + kk]);
                a[mt][1] = __float_as_uint(As[(mr + 8) * AST + kk]);
                a[mt][2] = __float_as_uint(As[mr * AST + kk + 4]);
                a[mt][3] = __float_as_uint(As[(mr + 8) * AST + kk + 4]);
            }
            #pragma unroll
            for (int nt = 0; nt < 8; nt++) {
                int nc = warpN * 64 + nt * 8 + gid;
                uint32_t b[2];
                b[0] = __float_as_uint(Bs[kk * BST + nc]);
                b[1] = __float_as_uint(Bs[(kk + 4) * BST + nc]);
                mma_tf32(C[0][nt], a[0], b);
                mma_tf32(C[1][nt], a[1], b);
            }
        }
    }

    // epilogue: dinv = rsqrt(1 + indeg), scale, write g_y
    #pragma unroll
    for (int mt = 0; mt < 2; mt++) {
        int gr0 = rowBase + warpM * 32 + mt * 16 + gid;
        int gr1 = gr0 + 8;
        float d0 = (gr0 < M) ? rsqrtf(1.0f + (float)g_icnt[gr0]) : 0.f;
        float d1 = (gr1 < M) ? rsqrtf(1.0f + (float)g_icnt[gr1]) : 0.f;
        #pragma unroll
        for (int nt = 0; nt < 8; nt++) {
            int col = colBase + warpN * 64 + nt * 8 + tig * 2;
            if (gr0 < M) {
                float2 v = make_float2(C[mt][nt][0] * d0, C[mt][nt][1] * d0);
                *(float2*)&g_y[(size_t)gr0 * DH + col] = v;
            }
            if (gr1 < M) {
                float2 v = make_float2(C[mt][nt][2] * d1, C[mt][nt][3] * d1);
                *(float2*)&g_y[(size_t)gr1 * DH + col] = v;
            }
        }
    }
}

// ================= CSR gather (padded CSR, warp per node, MLP~8) =================
// 32 lanes per node, each lane owns 8 columns (2 float4 per edge row).
// Indices fetched 4-at-a-time via broadcast int4 -> 8 independent float4 loads in flight.
template<bool LAYER2>
__global__ void __launch_bounds__(256)
k_gather(const int* __restrict__ batch, const float* __restrict__ bias, int N)
{
    int node = blockIdx.x * 8 + (threadIdx.x >> 5);
    if (node >= N) return;
    const int lane = threadIdx.x & 31;
    const size_t coff = (size_t)lane * 8;

    const int cnt0 = g_icnt[node];
    const int cnt = min(cnt0, CAP);
    if (!LAYER2 && lane == 0)
        atomicAdd(&g_cnt[batch[node]], 1.0f);

    float acc[8] = {0.f, 0.f, 0.f, 0.f, 0.f, 0.f, 0.f, 0.f};
    {   // self loop
        const float* p = g_y + (size_t)node * DH + coff;
        addf4(acc,     *(const float4*)p);
        addf4(acc + 4, *(const float4*)(p + 4));
    }

    const int4* ip = (const int4*)(g_eslot + node * CAP);   // CAP%4==0, aligned
    int j = 0;
    for (; j + 4 <= cnt; j += 4) {
        int4 s4 = ip[j >> 2];
        const float* p0 = g_y + (size_t)s4.x * DH + coff;
        const float* p1 = g_y + (size_t)s4.y * DH + coff;
        const float* p2 = g_y + (size_t)s4.z * DH + coff;
        const float* p3 = g_y + (size_t)s4.w * DH + coff;
        float4 a0 = *(const float4*)p0, b0 = *(const float4*)(p0 + 4);
        float4 a1 = *(const float4*)p1, b1 = *(const float4*)(p1 + 4);
        float4 a2 = *(const float4*)p2, b2 = *(const float4*)(p2 + 4);
        float4 a3 = *(const float4*)p3, b3 = *(const float4*)(p3 + 4);
        addf4(acc, a0); addf4(acc + 4, b0);
        addf4(acc, a1); addf4(acc + 4, b1);
        addf4(acc, a2); addf4(acc + 4, b2);
        addf4(acc, a3); addf4(acc + 4, b3);
    }
    for (; j < cnt; j++) {
        int s = g_eslot[node * CAP + j];
        const float* p = g_y + (size_t)s * DH + coff;
        addf4(acc,     *(const float4*)p);
        addf4(acc + 4, *(const float4*)(p + 4));
    }

    const float dv = rsqrtf(1.0f + (float)cnt0);
    float4 blo = *(const float4*)(bias + coff);
    float4 bhi = *(const float4*)(bias + coff + 4);
    float r[8];
    r[0] = fmaxf(fmaf(acc[0], dv, blo.x), 0.f);
    r[1] = fmaxf(fmaf(acc[1], dv, blo.y), 0.f);
    r[2] = fmaxf(fmaf(acc[2], dv, blo.z), 0.f);
    r[3] = fmaxf(fmaf(acc[3], dv, blo.w), 0.f);
    r[4] = fmaxf(fmaf(acc[4], dv, bhi.x), 0.f);
    r[5] = fmaxf(fmaf(acc[5], dv, bhi.y), 0.f);
    r[6] = fmaxf(fmaf(acc[6], dv, bhi.z), 0.f);
    r[7] = fmaxf(fmaf(acc[7], dv, bhi.w), 0.f);

    if (!LAYER2) {
        float* o = g_h + (size_t)node * DH + coff;
        *(float4*)o       = make_float4(r[0], r[1], r[2], r[3]);
        *(float4*)(o + 4) = make_float4(r[4], r[5], r[6], r[7]);
    } else {
        int g = batch[node];
        float* o = g_pool + (size_t)g * DH + coff;
        #pragma unroll
        for (int i = 0; i < 8; i++) atomicAdd(o + i, r[i]);
    }
}

// ================= final FC =================
__global__ void k_fc(const float* __restrict__ wfc, const float* __restrict__ bfc,
                     float* __restrict__ out)
{
    int w = (blockIdx.x * blockDim.x + threadIdx.x) >> 5;
    int lane = threadIdx.x & 31;
    if (w >= GNUM) return;
    float sum = 0.f;
    #pragma unroll
    for (int j = lane; j < DH; j += 32)
        sum += g_pool[w * DH + j] * wfc[j];
    #pragma unroll
    for (int o = 16; o; o >>= 1)
        sum += __shfl_xor_sync(0xffffffffu, sum, o);
    if (lane == 0)
        out[w] = sum / fmaxf(g_cnt[w], 1.f) + bfc[0];
}

// ================= launch =================
extern "C" void kernel_launch(void* const* d_in, const int* in_sizes, int n_in,
                              void* d_out, int out_size)
{
    const float* x     = (const float*)d_in[0];
    const int*   ei    = (const int*)  d_in[1];
    const int*   batch = (const int*)  d_in[2];
    const float* W1    = (const float*)d_in[3];
    const float* b1    = (const float*)d_in[4];
    const float* W2    = (const float*)d_in[5];
    const float* b2    = (const float*)d_in[6];
    const float* wfc   = (const float*)d_in[7];
    const float* bfc   = (const float*)d_in[8];
    float* out = (float*)d_out;

    const int N = in_sizes[2];        // 20000
    const int E = in_sizes[1] / 2;    // 320000
    const int* src = ei;
    const int* dst = ei + E;

    cudaFuncSetAttribute(k_gemm_mma<DIN, false>,
                         cudaFuncAttributeMaxDynamicSharedMemorySize, SMEM_GEMM_BYTES);
    cudaFuncSetAttribute(k_gemm_mma<DH, true>,
                         cudaFuncAttributeMaxDynamicSharedMemorySize, SMEM_GEMM_BYTES);

    // prep: 2 kernels total
    int zthreads = (GNUM * DH > N) ? GNUM * DH : N;
    k_zero<<<(zthreads + 255) / 256, 256>>>(N);
    k_fill<<<(E + 255) / 256, 256>>>(src, dst, E);

    dim3 gemm_grid((N + 159) / 160, DH / 128);
    const int gat_blocks = (N + 7) / 8;

    // layer 1
    k_gemm_mma<DIN, false><<<gemm_grid, 320, SMEM_GEMM_BYTES>>>(x, W1, N);
    k_gather<false><<<gat_blocks, 256>>>(batch, b1, N);

    // layer 2
    k_gemm_mma<DH, true><<<gemm_grid, 320, SMEM_GEMM_BYTES>>>(x /*unused*/, W2, N);
    k_gather<true><<<gat_blocks, 256>>>(batch, b2, N);

    // fc
    k_fc<<<GNUM * 32 / 128, 128>>>(wfc, bfc, out);
}

// round 9
// speedup vs baseline: 1.2888x; 1.2888x over previous
#include <cuda_runtime.h>
#include <cstdint>

#define DIN 512
#define DH  256
#define GNUM 128
#define NMAX 20000
#define EMAX 320000
#define CAP  96          // padded-CSR slots per node (Poisson(16) -> max deg ~45)

// ---- scratch (static __device__ globals; zero-initialized at load) ----
__device__ float g_y[NMAX * DH];       // messages y = (A@W)*dinv[row]
__device__ float g_h[NMAX * DH];       // layer-1 output (GEMM-2 input)
__device__ int   g_icnt[NMAX];         // in-degree (excl. self); cleared by gather<1>
__device__ int   g_eslot[NMAX * CAP];  // padded CSR: src per incoming edge
__device__ float g_pool[GNUM * DH];    // cleared by k_fc after read
__device__ float g_cnt[GNUM];          // cleared by k_fc after read

// ================= helpers =================
__device__ __forceinline__ float tf32r(float x) {
    uint32_t u;
    asm("cvt.rna.tf32.f32 %0, %1;" : "=r"(u) : "f"(x));
    return __uint_as_float(u);
}

__device__ __forceinline__ void mma_tf32(float* c, const uint32_t* a, const uint32_t* b) {
    asm volatile("mma.sync.aligned.m16n8k8.row.col.f32.tf32.tf32.f32 "
        "{%0,%1,%2,%3}, {%4,%5,%6,%7}, {%8,%9}, {%0,%1,%2,%3};"
        : "+f"(c[0]), "+f"(c[1]), "+f"(c[2]), "+f"(c[3])
        : "r"(a[0]), "r"(a[1]), "r"(a[2]), "r"(a[3]), "r"(b[0]), "r"(b[1]));
}

__device__ __forceinline__ void addf4(float* a, float4 v) {
    a[0] += v.x; a[1] += v.y; a[2] += v.z; a[3] += v.w;
}

// ================= prep: padded-CSR fill (icnt pre-zeroed by pipeline) =================
__global__ void k_fill(const int* __restrict__ src, const int* __restrict__ dst, int E) {
    int e = blockIdx.x * blockDim.x + threadIdx.x;
    if (e >= E) return;
    int d = dst[e];
    int pos = atomicAdd(&g_icnt[d], 1);
    if (pos < CAP) g_eslot[d * CAP + pos] = src[e];
}

// ================= TF32 mma.sync GEMM: g_y = (A @ W) * dinv[row] =================
// CTA tile 160x128, BK=32, 10 warps, warptile 32x64 (2x8 m16n8k8 tiles).
#define AST 36
#define BST 136
#define AS_F (160 * AST)
#define BS_F (32 * BST)
#define SMEM_GEMM_BYTES ((2 * AS_F + 2 * BS_F) * 4)

template<int K, bool FROM_H>
__global__ void __launch_bounds__(320, 2)
k_gemm_mma(const float* __restrict__ Ax, const float* __restrict__ W, int M)
{
    extern __shared__ float sm[];
    const float* __restrict__ A = FROM_H ? (const float*)g_h : Ax;

    const int tid = threadIdx.x;
    const int wid = tid >> 5;
    const int lid = tid & 31;
    const int gid = lid >> 2;
    const int tig = lid & 3;
    const int warpM = wid % 5;
    const int warpN = wid / 5;
    const int rowBase = blockIdx.x * 160;
    const int colBase = blockIdx.y * 128;
    constexpr int NC = K / 32;

    float C[2][8][4];
    #pragma unroll
    for (int mt = 0; mt < 2; mt++)
        #pragma unroll
        for (int nt = 0; nt < 8; nt++)
            #pragma unroll
            for (int i = 0; i < 4; i++) C[mt][nt][i] = 0.f;

    auto stage = [&](int buf, int c) {
        float* As = sm + buf * AS_F;
        float* Bs = sm + 2 * AS_F + buf * BS_F;
        #pragma unroll
        for (int i = 0; i < 4; i++) {
            int idx = tid + i * 320;
            int m = idx >> 3, k4 = (idx & 7) << 2;
            int gr = rowBase + m;
            float4 v = make_float4(0.f, 0.f, 0.f, 0.f);
            if (gr < M) v = *(const float4*)(A + (size_t)gr * K + c * 32 + k4);
            v.x = tf32r(v.x); v.y = tf32r(v.y); v.z = tf32r(v.z); v.w = tf32r(v.w);
            *(float4*)&As[m * AST + k4] = v;
        }
        #pragma unroll
        for (int i = 0; i < 4; i++) {
            int idx = tid + i * 320;
            if (idx < 1024) {
                int k = idx >> 5, n4 = (idx & 31) << 2;
                float4 v = *(const float4*)(W + (size_t)(c * 32 + k) * DH + colBase + n4);
                v.x = tf32r(v.x); v.y = tf32r(v.y); v.z = tf32r(v.z); v.w = tf32r(v.w);
                *(float4*)&Bs[k * BST + n4] = v;
            }
        }
    };

    stage(0, 0);

    for (int c = 0; c < NC; c++) {
        __syncthreads();
        if (c + 1 < NC) stage((c + 1) & 1, c + 1);

        const int buf = c & 1;
        const float* As = sm + buf * AS_F;
        const float* Bs = sm + 2 * AS_F + buf * BS_F;

        #pragma unroll
        for (int ks = 0; ks < 4; ks++) {
            const int kk = ks * 8 + tig;
            uint32_t a[2][4];
            #pragma unroll
            for (int mt = 0; mt < 2; mt++) {
                int mr = warpM * 32 + mt * 16 + gid;
                a[mt][0] = __float_as_uint(As[mr * AST + kk]);
                a[mt][1] = __float_as_uint(As[(mr + 8) * AST + kk]);
                a[mt][2] = __float_as_uint(As[mr * AST + kk + 4]);
                a[mt][3] = __float_as_uint(As[(mr + 8) * AST + kk + 4]);
            }
            #pragma unroll
            for (int nt = 0; nt < 8; nt++) {
                int nc = warpN * 64 + nt * 8 + gid;
                uint32_t b[2];
                b[0] = __float_as_uint(Bs[kk * BST + nc]);
                b[1] = __float_as_uint(Bs[(kk + 4) * BST + nc]);
                mma_tf32(C[0][nt], a[0], b);
                mma_tf32(C[1][nt], a[1], b);
            }
        }
    }

    // epilogue: dinv = rsqrt(1 + indeg), scale, write g_y
    #pragma unroll
    for (int mt = 0; mt < 2; mt++) {
        int gr0 = rowBase + warpM * 32 + mt * 16 + gid;
        int gr1 = gr0 + 8;
        float d0 = (gr0 < M) ? rsqrtf(1.0f + (float)g_icnt[gr0]) : 0.f;
        float d1 = (gr1 < M) ? rsqrtf(1.0f + (float)g_icnt[gr1]) : 0.f;
        #pragma unroll
        for (int nt = 0; nt < 8; nt++) {
            int col = colBase + warpN * 64 + nt * 8 + tig * 2;
            if (gr0 < M) {
                float2 v = make_float2(C[mt][nt][0] * d0, C[mt][nt][1] * d0);
                *(float2*)&g_y[(size_t)gr0 * DH + col] = v;
            }
            if (gr1 < M) {
                float2 v = make_float2(C[mt][nt][2] * d1, C[mt][nt][3] * d1);
                *(float2*)&g_y[(size_t)gr1 * DH + col] = v;
            }
        }
    }
}

// ================= CSR gather: 64 threads/node (r7 shape), 8-deep load batches =================
// LAYER1: writes g_h, accumulates group counts.
// LAYER2: block-aggregated mean-pool (sorted batch -> smem tile), clears g_icnt.
template<bool LAYER2>
__global__ void __launch_bounds__(256)
k_gather(const int* __restrict__ batch, const float* __restrict__ bias, int N)
{
    __shared__ float sp[DH];
    __shared__ int sg;

    const int node = blockIdx.x * 4 + (threadIdx.x >> 6);
    const bool valid = node < N;
    const int c = (threadIdx.x & 63) << 2;

    if (LAYER2) {
        sp[threadIdx.x] = 0.f;
        if (threadIdx.x == 0) sg = batch[min(blockIdx.x * 4, N - 1)];
        __syncthreads();
    } else {
        if (!valid) return;
    }

    float acc[4] = {0.f, 0.f, 0.f, 0.f};
    int cnt0 = 0;

    if (valid) {
        cnt0 = g_icnt[node];
        const int cnt = min(cnt0, CAP);
        if (!LAYER2 && (threadIdx.x & 63) == 0)
            atomicAdd(&g_cnt[batch[node]], 1.0f);

        addf4(acc, *(const float4*)(g_y + (size_t)node * DH + c));   // self loop

        const int4* ip = (const int4*)(g_eslot + node * CAP);        // CAP%4==0
        int j = 0;
        for (; j + 8 <= cnt; j += 8) {
            int4 sA = ip[j >> 2];
            int4 sB = ip[(j >> 2) + 1];
            float4 v0 = *(const float4*)(g_y + (size_t)sA.x * DH + c);
            float4 v1 = *(const float4*)(g_y + (size_t)sA.y * DH + c);
            float4 v2 = *(const float4*)(g_y + (size_t)sA.z * DH + c);
            float4 v3 = *(const float4*)(g_y + (size_t)sA.w * DH + c);
            float4 v4 = *(const float4*)(g_y + (size_t)sB.x * DH + c);
            float4 v5 = *(const float4*)(g_y + (size_t)sB.y * DH + c);
            float4 v6 = *(const float4*)(g_y + (size_t)sB.z * DH + c);
            float4 v7 = *(const float4*)(g_y + (size_t)sB.w * DH + c);
            addf4(acc, v0); addf4(acc, v1); addf4(acc, v2); addf4(acc, v3);
            addf4(acc, v4); addf4(acc, v5); addf4(acc, v6); addf4(acc, v7);
        }
        if (j + 4 <= cnt) {
            int4 sA = ip[j >> 2];
            float4 v0 = *(const float4*)(g_y + (size_t)sA.x * DH + c);
            float4 v1 = *(const float4*)(g_y + (size_t)sA.y * DH + c);
            float4 v2 = *(const float4*)(g_y + (size_t)sA.z * DH + c);
            float4 v3 = *(const float4*)(g_y + (size_t)sA.w * DH + c);
            addf4(acc, v0); addf4(acc, v1); addf4(acc, v2); addf4(acc, v3);
            j += 4;
        }
        for (; j < cnt; j++) {
            int s = g_eslot[node * CAP + j];
            addf4(acc, *(const float4*)(g_y + (size_t)s * DH + c));
        }
    }

    if (!LAYER2) {
        const float dv = rsqrtf(1.0f + (float)cnt0);
        float4 b = *(const float4*)(bias + c);
        float4 r;
        r.x = fmaxf(fmaf(acc[0], dv, b.x), 0.f);
        r.y = fmaxf(fmaf(acc[1], dv, b.y), 0.f);
        r.z = fmaxf(fmaf(acc[2], dv, b.z), 0.f);
        r.w = fmaxf(fmaf(acc[3], dv, b.w), 0.f);
        *(float4*)(g_h + (size_t)node * DH + c) = r;
    } else {
        if (valid) {
            const float dv = rsqrtf(1.0f + (float)cnt0);
            float4 b = *(const float4*)(bias + c);
            float r[4];
            r[0] = fmaxf(fmaf(acc[0], dv, b.x), 0.f);
            r[1] = fmaxf(fmaf(acc[1], dv, b.y), 0.f);
            r[2] = fmaxf(fmaf(acc[2], dv, b.z), 0.f);
            r[3] = fmaxf(fmaf(acc[3], dv, b.w), 0.f);
            int g = batch[node];
            if (g == sg) {
                #pragma unroll
                for (int i = 0; i < 4; i++) atomicAdd(&sp[c + i], r[i]);
            } else {
                #pragma unroll
                for (int i = 0; i < 4; i++) atomicAdd(&g_pool[(size_t)g * DH + c + i], r[i]);
            }
            if ((threadIdx.x & 63) == 0) g_icnt[node] = 0;   // self-clean for next launch
        }
        __syncthreads();
        atomicAdd(&g_pool[(size_t)sg * DH + threadIdx.x], sp[threadIdx.x]);
    }
}

// ================= final FC (+ scratch clear) =================
__global__ void k_fc(const float* __restrict__ wfc, const float* __restrict__ bfc,
                     float* __restrict__ out)
{
    int w = (blockIdx.x * blockDim.x + threadIdx.x) >> 5;
    int lane = threadIdx.x & 31;
    if (w >= GNUM) return;
    float sum = 0.f;
    #pragma unroll
    for (int j = lane; j < DH; j += 32) {
        sum += g_pool[w * DH + j] * wfc[j];
        g_pool[w * DH + j] = 0.f;          // self-clean
    }
    #pragma unroll
    for (int o = 16; o; o >>= 1)
        sum += __shfl_xor_sync(0xffffffffu, sum, o);
    if (lane == 0) {
        float cntw = g_cnt[w];
        g_cnt[w] = 0.f;                    // self-clean
        out[w] = sum / fmaxf(cntw, 1.f) + bfc[0];
    }
}

// ================= launch =================
extern "C" void kernel_launch(void* const* d_in, const int* in_sizes, int n_in,
                              void* d_out, int out_size)
{
    const float* x     = (const float*)d_in[0];
    const int*   ei    = (const int*)  d_in[1];
    const int*   batch = (const int*)  d_in[2];
    const float* W1    = (const float*)d_in[3];
    const float* b1    = (const float*)d_in[4];
    const float* W2    = (const float*)d_in[5];
    const float* b2    = (const float*)d_in[6];
    const float* wfc   = (const float*)d_in[7];
    const float* bfc   = (const float*)d_in[8];
    float* out = (float*)d_out;

    const int N = in_sizes[2];        // 20000
    const int E = in_sizes[1] / 2;    // 320000
    const int* src = ei;
    const int* dst = ei + E;

    cudaFuncSetAttribute(k_gemm_mma<DIN, false>,
                         cudaFuncAttributeMaxDynamicSharedMemorySize, SMEM_GEMM_BYTES);
    cudaFuncSetAttribute(k_gemm_mma<DH, true>,
                         cudaFuncAttributeMaxDynamicSharedMemorySize, SMEM_GEMM_BYTES);

    // prep: single kernel (g_icnt arrives zeroed: static init / previous launch)
    k_fill<<<(E + 255) / 256, 256>>>(src, dst, E);

    dim3 gemm_grid((N + 159) / 160, DH / 128);
    const int gat_blocks = (N + 3) / 4;

    // layer 1
    k_gemm_mma<DIN, false><<<gemm_grid, 320, SMEM_GEMM_BYTES>>>(x, W1, N);
    k_gather<false><<<gat_blocks, 256>>>(batch, b1, N);

    // layer 2
    k_gemm_mma<DH, true><<<gemm_grid, 320, SMEM_GEMM_BYTES>>>(x /*unused*/, W2, N);
    k_gather<true><<<gat_blocks, 256>>>(batch, b2, N);

    // fc (also clears pool/cnt for next launch)
    k_fc<<<GNUM * 32 / 128, 128>>>(wfc, bfc, out);
}

// round 10
// speedup vs baseline: 1.5266x; 1.1845x over previous
#include <cuda_runtime.h>
#include <cstdint>

#define DIN 512
#define DH  256
#define GNUM 128
#define NMAX 20000
#define EMAX 320000
#define CAP  96          // padded-CSR slots per node

// ---- scratch (static __device__ globals; zero-initialized at load) ----
__device__ float g_y[NMAX * DH];       // messages y = (A@W)*dinv[row]
__device__ float g_h[NMAX * DH];       // layer-1 output (tf32-grid, GEMM-2 input)
__device__ float g_xr[NMAX * DIN];     // x pre-rounded to tf32 grid
__device__ float g_w1r[DIN * DH];      // W1 pre-rounded
__device__ float g_w2r[DH * DH];       // W2 pre-rounded
__device__ int   g_icnt[NMAX];         // in-degree (excl. self); cleared by gather<1>
__device__ int   g_eslot[NMAX * CAP];  // padded CSR: src per incoming edge
__device__ float g_pool[GNUM * DH];    // cleared by k_fc after read
__device__ float g_cnt[GNUM];          // cleared by k_fc after read

// ================= helpers =================
__device__ __forceinline__ float tf32r(float x) {
    uint32_t u;
    asm("cvt.rna.tf32.f32 %0, %1;" : "=r"(u) : "f"(x));
    return __uint_as_float(u);
}

__device__ __forceinline__ uint32_t smem_u32(const void* p) {
    uint32_t a;
    asm("{ .reg .u64 t; cvta.to.shared.u64 t, %1; cvt.u32.u64 %0, t; }" : "=r"(a) : "l"(p));
    return a;
}

__device__ __forceinline__ void mma_tf32(float* c, const uint32_t* a, const uint32_t* b) {
    asm volatile("mma.sync.aligned.m16n8k8.row.col.f32.tf32.tf32.f32 "
        "{%0,%1,%2,%3}, {%4,%5,%6,%7}, {%8,%9}, {%0,%1,%2,%3};"
        : "+f"(c[0]), "+f"(c[1]), "+f"(c[2]), "+f"(c[3])
        : "r"(a[0]), "r"(a[1]), "r"(a[2]), "r"(a[3]), "r"(b[0]), "r"(b[1]));
}

__device__ __forceinline__ void addf4(float* a, float4 v) {
    a[0] += v.x; a[1] += v.y; a[2] += v.z; a[3] += v.w;
}

// ================= fused prep: CSR fill + tf32-round x, W1, W2 =================
__global__ void k_prep(const int* __restrict__ src, const int* __restrict__ dst,
                       const float* __restrict__ x, const float* __restrict__ W1,
                       const float* __restrict__ W2, int E, int N)
{
    const int FILL_B = (E + 255) / 256;
    const int XR_Q   = N * DIN / 4;
    const int XR_B   = (XR_Q + 255) / 256;
    const int W1_B   = (DIN * DH / 4) / 256;
    const int b = blockIdx.x;

    if (b < FILL_B) {
        int e = b * 256 + threadIdx.x;
        if (e < E) {
            int d = dst[e];
            int pos = atomicAdd(&g_icnt[d], 1);
            if (pos < CAP) g_eslot[d * CAP + pos] = src[e];
        }
    } else if (b < FILL_B + XR_B) {
        int q = (b - FILL_B) * 256 + threadIdx.x;
        if (q < XR_Q) {
            float4 v = ((const float4*)x)[q];
            v.x = tf32r(v.x); v.y = tf32r(v.y); v.z = tf32r(v.z); v.w = tf32r(v.w);
            ((float4*)g_xr)[q] = v;
        }
    } else if (b < FILL_B + XR_B + W1_B) {
        int q = (b - FILL_B - XR_B) * 256 + threadIdx.x;
        float4 v = ((const float4*)W1)[q];
        v.x = tf32r(v.x); v.y = tf32r(v.y); v.z = tf32r(v.z); v.w = tf32r(v.w);
        ((float4*)g_w1r)[q] = v;
    } else {
        int q = (b - FILL_B - XR_B - W1_B) * 256 + threadIdx.x;
        if (q < DH * DH / 4) {
            float4 v = ((const float4*)W2)[q];
            v.x = tf32r(v.x); v.y = tf32r(v.y); v.z = tf32r(v.z); v.w = tf32r(v.w);
            ((float4*)g_w2r)[q] = v;
        }
    }
}

// ================= TF32 GEMM, cp.async 3-stage: g_y = (A @ W) * dinv[row] =================
// CTA 160 x 256 (full N), 640 threads (20 warps, 5x4), warptile 32x64.
// Stage: A 160x32 (stride 36), B 32x256 (stride 264); operands pre-rounded to tf32 grid.
#define AST 36
#define BST 264
#define A_F (160 * AST)            // 5760 floats
#define B_F (32 * BST)             // 8448 floats
#define STG_F (A_F + B_F)          // 14208 floats
#define SMEM_GEMM_BYTES (3 * STG_F * 4)   // 170496 B

template<int K>
__global__ void __launch_bounds__(640, 1)
k_gemm_cp(const float* __restrict__ A, const float* __restrict__ W, int M)
{
    extern __shared__ float sm[];
    const uint32_t sbase = smem_u32(sm);

    const int tid = threadIdx.x;
    const int wid = tid >> 5;
    const int lid = tid & 31;
    const int gid = lid >> 2;
    const int tig = lid & 3;
    const int warpM = wid % 5;        // 0..4
    const int warpN = wid / 5;        // 0..3
    const int rowBase = blockIdx.x * 160;
    constexpr int NC = K / 32;

    float C[2][8][4];
    #pragma unroll
    for (int mt = 0; mt < 2; mt++)
        #pragma unroll
        for (int nt = 0; nt < 8; nt++)
            #pragma unroll
            for (int i = 0; i < 4; i++) C[mt][nt][i] = 0.f;

    auto stage = [&](int buf, int c) {
        uint32_t Asb = sbase + buf * (STG_F * 4);
        uint32_t Bsb = Asb + A_F * 4;
        // A chunk: 160x32 floats = 1280 float4
        #pragma unroll
        for (int i = 0; i < 2; i++) {
            int idx = tid + i * 640;
            int m = idx >> 3, k4 = (idx & 7) << 2;
            const float* s = A + (size_t)(rowBase + m) * K + c * 32 + k4;
            uint32_t d = Asb + (uint32_t)(m * AST + k4) * 4;
            int sz = (rowBase + m < M) ? 16 : 0;
            asm volatile("cp.async.cg.shared.global [%0], [%1], 16, %2;"
                         :: "r"(d), "l"(s), "r"(sz) : "memory");
        }
        // B chunk: 32x256 floats = 2048 float4
        #pragma unroll
        for (int i = 0; i < 4; i++) {
            int idx = tid + i * 640;
            if (idx < 2048) {
                int k = idx >> 6, n4 = (idx & 63) << 2;
                const float* s = W + (size_t)(c * 32 + k) * DH + n4;
                uint32_t d = Bsb + (uint32_t)(k * BST + n4) * 4;
                asm volatile("cp.async.cg.shared.global [%0], [%1], 16;"
                             :: "r"(d), "l"(s) : "memory");
            }
        }
    };

    stage(0, 0);
    asm volatile("cp.async.commit_group;" ::: "memory");
    if (NC > 1) {
        stage(1, 1);
        asm volatile("cp.async.commit_group;" ::: "memory");
    }

    for (int c = 0; c < NC; c++) {
        if (c + 1 < NC) asm volatile("cp.async.wait_group 1;" ::: "memory");
        else            asm volatile("cp.async.wait_group 0;" ::: "memory");
        __syncthreads();
        if (c + 2 < NC) {
            stage((c + 2) % 3, c + 2);
            asm volatile("cp.async.commit_group;" ::: "memory");
        }

        const float* As = sm + (c % 3) * STG_F;
        const float* Bs = As + A_F;

        #pragma unroll
        for (int ks = 0; ks < 4; ks++) {
            const int kk = ks * 8 + tig;
            uint32_t a[2][4];
            #pragma unroll
            for (int mt = 0; mt < 2; mt++) {
                int mr = warpM * 32 + mt * 16 + gid;
                a[mt][0] = __float_as_uint(As[mr * AST + kk]);
                a[mt][1] = __float_as_uint(As[(mr + 8) * AST + kk]);
                a[mt][2] = __float_as_uint(As[mr * AST + kk + 4]);
                a[mt][3] = __float_as_uint(As[(mr + 8) * AST + kk + 4]);
            }
            #pragma unroll
            for (int nt = 0; nt < 8; nt++) {
                int nc = warpN * 64 + nt * 8 + gid;
                uint32_t b[2];
                b[0] = __float_as_uint(Bs[kk * BST + nc]);
                b[1] = __float_as_uint(Bs[(kk + 4) * BST + nc]);
                mma_tf32(C[0][nt], a[0], b);
                mma_tf32(C[1][nt], a[1], b);
            }
        }
    }

    // epilogue: dinv = rsqrt(1 + indeg), scale, write g_y
    #pragma unroll
    for (int mt = 0; mt < 2; mt++) {
        int gr0 = rowBase + warpM * 32 + mt * 16 + gid;
        int gr1 = gr0 + 8;
        float d0 = (gr0 < M) ? rsqrtf(1.0f + (float)g_icnt[gr0]) : 0.f;
        float d1 = (gr1 < M) ? rsqrtf(1.0f + (float)g_icnt[gr1]) : 0.f;
        #pragma unroll
        for (int nt = 0; nt < 8; nt++) {
            int col = warpN * 64 + nt * 8 + tig * 2;
            if (gr0 < M) {
                float2 v = make_float2(C[mt][nt][0] * d0, C[mt][nt][1] * d0);
                *(float2*)&g_y[(size_t)gr0 * DH + col] = v;
            }
            if (gr1 < M) {
                float2 v = make_float2(C[mt][nt][2] * d1, C[mt][nt][3] * d1);
                *(float2*)&g_y[(size_t)gr1 * DH + col] = v;
            }
        }
    }
}

// ================= CSR gather: 64 threads/node, 8-deep load batches =================
// LAYER1: writes g_h (tf32-rounded), accumulates group counts.
// LAYER2: block-aggregated mean-pool (sorted batch -> smem tile), clears g_icnt.
template<bool LAYER2>
__global__ void __launch_bounds__(256)
k_gather(const int* __restrict__ batch, const float* __restrict__ bias, int N)
{
    __shared__ float sp[DH];
    __shared__ int sg;

    const int node = blockIdx.x * 4 + (threadIdx.x >> 6);
    const bool valid = node < N;
    const int c = (threadIdx.x & 63) << 2;

    if (LAYER2) {
        sp[threadIdx.x] = 0.f;
        if (threadIdx.x == 0) sg = batch[min(blockIdx.x * 4, N - 1)];
        __syncthreads();
    } else {
        if (!valid) return;
    }

    float acc[4] = {0.f, 0.f, 0.f, 0.f};
    int cnt0 = 0;

    if (valid) {
        cnt0 = g_icnt[node];
        const int cnt = min(cnt0, CAP);
        if (!LAYER2 && (threadIdx.x & 63) == 0)
            atomicAdd(&g_cnt[batch[node]], 1.0f);

        addf4(acc, *(const float4*)(g_y + (size_t)node * DH + c));   // self loop

        const int4* ip = (const int4*)(g_eslot + node * CAP);        // CAP%4==0
        int j = 0;
        for (; j + 8 <= cnt; j += 8) {
            int4 sA = ip[j >> 2];
            int4 sB = ip[(j >> 2) + 1];
            float4 v0 = *(const float4*)(g_y + (size_t)sA.x * DH + c);
            float4 v1 = *(const float4*)(g_y + (size_t)sA.y * DH + c);
            float4 v2 = *(const float4*)(g_y + (size_t)sA.z * DH + c);
            float4 v3 = *(const float4*)(g_y + (size_t)sA.w * DH + c);
            float4 v4 = *(const float4*)(g_y + (size_t)sB.x * DH + c);
            float4 v5 = *(const float4*)(g_y + (size_t)sB.y * DH + c);
            float4 v6 = *(const float4*)(g_y + (size_t)sB.z * DH + c);
            float4 v7 = *(const float4*)(g_y + (size_t)sB.w * DH + c);
            addf4(acc, v0); addf4(acc, v1); addf4(acc, v2); addf4(acc, v3);
            addf4(acc, v4); addf4(acc, v5); addf4(acc, v6); addf4(acc, v7);
        }
        if (j + 4 <= cnt) {
            int4 sA = ip[j >> 2];
            float4 v0 = *(const float4*)(g_y + (size_t)sA.x * DH + c);
            float4 v1 = *(const float4*)(g_y + (size_t)sA.y * DH + c);
            float4 v2 = *(const float4*)(g_y + (size_t)sA.z * DH + c);
            float4 v3 = *(const float4*)(g_y + (size_t)sA.w * DH + c);
            addf4(acc, v0); addf4(acc, v1); addf4(acc, v2); addf4(acc, v3);
            j += 4;
        }
        for (; j < cnt; j++) {
            int s = g_eslot[node * CAP + j];
            addf4(acc, *(const float4*)(g_y + (size_t)s * DH + c));
        }
    }

    if (!LAYER2) {
        const float dv = rsqrtf(1.0f + (float)cnt0);
        float4 b = *(const float4*)(bias + c);
        float4 r;
        r.x = tf32r(fmaxf(fmaf(acc[0], dv, b.x), 0.f));   // pre-round for GEMM2
        r.y = tf32r(fmaxf(fmaf(acc[1], dv, b.y), 0.f));
        r.z = tf32r(fmaxf(fmaf(acc[2], dv, b.z), 0.f));
        r.w = tf32r(fmaxf(fmaf(acc[3], dv, b.w), 0.f));
        *(float4*)(g_h + (size_t)node * DH + c) = r;
    } else {
        if (valid) {
            const float dv = rsqrtf(1.0f + (float)cnt0);
            float4 b = *(const float4*)(bias + c);
            float r[4];
            r[0] = fmaxf(fmaf(acc[0], dv, b.x), 0.f);
            r[1] = fmaxf(fmaf(acc[1], dv, b.y), 0.f);
            r[2] = fmaxf(fmaf(acc[2], dv, b.z), 0.f);
            r[3] = fmaxf(fmaf(acc[3], dv, b.w), 0.f);
            int g = batch[node];
            if (g == sg) {
                #pragma unroll
                for (int i = 0; i < 4; i++) atomicAdd(&sp[c + i], r[i]);
            } else {
                #pragma unroll
                for (int i = 0; i < 4; i++) atomicAdd(&g_pool[(size_t)g * DH + c + i], r[i]);
            }
            if ((threadIdx.x & 63) == 0) g_icnt[node] = 0;   // self-clean for next launch
        }
        __syncthreads();
        atomicAdd(&g_pool[(size_t)sg * DH + threadIdx.x], sp[threadIdx.x]);
    }
}

// ================= final FC (+ scratch clear) =================
__global__ void k_fc(const float* __restrict__ wfc, const float* __restrict__ bfc,
                     float* __restrict__ out)
{
    int w = (blockIdx.x * blockDim.x + threadIdx.x) >> 5;
    int lane = threadIdx.x & 31;
    if (w >= GNUM) return;
    float sum = 0.f;
    #pragma unroll
    for (int j = lane; j < DH; j += 32) {
        sum += g_pool[w * DH + j] * wfc[j];
        g_pool[w * DH + j] = 0.f;          // self-clean
    }
    #pragma unroll
    for (int o = 16; o; o >>= 1)
        sum += __shfl_xor_sync(0xffffffffu, sum, o);
    if (lane == 0) {
        float cntw = g_cnt[w];
        g_cnt[w] = 0.f;                    // self-clean
        out[w] = sum / fmaxf(cntw, 1.f) + bfc[0];
    }
}

// ================= launch =================
extern "C" void kernel_launch(void* const* d_in, const int* in_sizes, int n_in,
                              void* d_out, int out_size)
{
    const float* x     = (const float*)d_in[0];
    const int*   ei    = (const int*)  d_in[1];
    const int*   batch = (const int*)  d_in[2];
    const float* W1    = (const float*)d_in[3];
    const float* b1    = (const float*)d_in[4];
    const float* W2    = (const float*)d_in[5];
    const float* b2    = (const float*)d_in[6];
    const float* wfc   = (const float*)d_in[7];
    const float* bfc   = (const float*)d_in[8];
    float* out = (float*)d_out;

    const int N = in_sizes[2];        // 20000
    const int E = in_sizes[1] / 2;    // 320000
    const int* src = ei;
    const int* dst = ei + E;

    cudaFuncSetAttribute(k_gemm_cp<DIN>,
                         cudaFuncAttributeMaxDynamicSharedMemorySize, SMEM_GEMM_BYTES);
    cudaFuncSetAttribute(k_gemm_cp<DH>,
                         cudaFuncAttributeMaxDynamicSharedMemorySize, SMEM_GEMM_BYTES);

    // fused prep: CSR fill + tf32-round x, W1, W2
    const int FILL_B = (E + 255) / 256;
    const int XR_B   = (N * DIN / 4 + 255) / 256;
    const int W1_B   = (DIN * DH / 4) / 256;
    const int W2_B   = (DH * DH / 4) / 256;
    k_prep<<<FILL_B + XR_B + W1_B + W2_B, 256>>>(src, dst, x, W1, W2, E, N);

    float* xr;  cudaGetSymbolAddress((void**)&xr, g_xr);
    float* w1r; cudaGetSymbolAddress((void**)&w1r, g_w1r);
    float* w2r; cudaGetSymbolAddress((void**)&w2r, g_w2r);
    float* h;   cudaGetSymbolAddress((void**)&h, g_h);

    const int gemm_blocks = (N + 159) / 160;   // 125
    const int gat_blocks  = (N + 3) / 4;

    // layer 1
    k_gemm_cp<DIN><<<gemm_blocks, 640, SMEM_GEMM_BYTES>>>(xr, w1r, N);
    k_gather<false><<<gat_blocks, 256>>>(batch, b1, N);

    // layer 2
    k_gemm_cp<DH><<<gemm_blocks, 640, SMEM_GEMM_BYTES>>>(h, w2r, N);
    k_gather<true><<<gat_blocks, 256>>>(batch, b2, N);

    // fc (also clears pool/cnt for next launch)
    k_fc<<<GNUM * 32 / 128, 128>>>(wfc, bfc, out);
}